// round 15
// baseline (speedup 1.0000x reference)
#include <cuda_runtime.h>

// TT-linear: y = x @ W^T + bias
//   c0: [1,32(o0),32(i0),4(r1)]  c1: [4(r1),16(o1),16(i1),4(r2)]  c2: [4(r2),16(o2),16(i2),1]
//
// Stage A: grid 512 = (token-pair 64) x (i0-eighth 8); 256 thr; occ 4 (no yp -> low regs).
//   R13's steps 1-2 verbatim (dual-o1, dual-token amortization, 1 barrier/slice),
//   writes B[o1][t][i0][o2][r1] to scratch via coalesced STG.64 (z picks r1-pair).
// Stage B: grid 512 = (o1 16) x (token-quad 32); 256 thr; occ 4; barrier-free GEMM:
//   y[t,o0,o1,o2] = sum_{i0,r1} B * c0[o0,i0,r1] + bias, direct STG (no atomics).

#define THREADS 256

typedef unsigned long long u64;

__device__ float g_B[16u * 128u * 32u * 16u * 4u];   // [o1][t][i0][o2][r1] 16.8MB

__device__ __forceinline__ u64 pk2(float lo, float hi) {
    u64 r;
    asm("mov.b64 %0, {%1, %2};" : "=l"(r) : "f"(lo), "f"(hi));
    return r;
}
__device__ __forceinline__ void unpk(u64 v, float& lo, float& hi) {
    asm("mov.b64 {%0, %1}, %2;" : "=f"(lo), "=f"(hi) : "l"(v));
}
__device__ __forceinline__ u64 fma2(u64 a, u64 b, u64 c) {
    u64 d;
    asm("fma.rn.f32x2 %0, %1, %2, %3;" : "=l"(d) : "l"(a), "l"(b), "l"(c));
    return d;
}
__device__ __forceinline__ float hadd(u64 v) {
    float lo, hi;
    unpk(v, lo, hi);
    return lo + hi;
}

// step1: A_t[i1][o2][r2] for BOTH tokens, one i1 row, shared c2 loads. (R13 verbatim)
__device__ __forceinline__ void step1_both(const float* __restrict__ Xs0,
                                           const float* __restrict__ Xs1,
                                           float* __restrict__ Ad0,
                                           float* __restrict__ Ad1,
                                           const float* __restrict__ sc2,
                                           int i1, int o2)
{
    u64 a01_0 = 0ull, a23_0 = 0ull, a01_1 = 0ull, a23_1 = 0ull;
    #pragma unroll
    for (int ch = 0; ch < 2; ch++) {
        const float4* xq0 = reinterpret_cast<const float4*>(&Xs0[i1 * 16 + ch * 8]);
        const float4* xq1 = reinterpret_cast<const float4*>(&Xs1[i1 * 16 + ch * 8]);
        float4 p0 = xq0[0], p1 = xq0[1];
        float4 q0 = xq1[0], q1 = xq1[1];
        float xs0[8] = { p0.x,p0.y,p0.z,p0.w, p1.x,p1.y,p1.z,p1.w };
        float xs1[8] = { q0.x,q0.y,q0.z,q0.w, q1.x,q1.y,q1.z,q1.w };
        #pragma unroll
        for (int j = 0; j < 8; j++) {
            const int i2 = ch * 8 + j;
            ulonglong2 c = *reinterpret_cast<const ulonglong2*>(&sc2[(i2 * 16 + o2) * 4]);
            u64 xd0 = pk2(xs0[j], xs0[j]);
            u64 xd1 = pk2(xs1[j], xs1[j]);
            a01_0 = fma2(xd0, c.x, a01_0);
            a23_0 = fma2(xd0, c.y, a23_0);
            a01_1 = fma2(xd1, c.x, a01_1);
            a23_1 = fma2(xd1, c.y, a23_1);
        }
    }
    ulonglong2 st0; st0.x = a01_0; st0.y = a23_0;
    ulonglong2 st1; st1.x = a01_1; st1.y = a23_1;
    *reinterpret_cast<ulonglong2*>(&Ad0[(i1 * 16 + o2) * 4]) = st0;
    *reinterpret_cast<ulonglong2*>(&Ad1[(i1 * 16 + o2) * 4]) = st1;
}

__global__ __launch_bounds__(THREADS, 4)
void tt_stageA_kernel(const float* __restrict__ x,
                      const float* __restrict__ g1,
                      const float* __restrict__ g2)
{
    __shared__ __align__(16) float sc1[4096];       // [o1 16][i1 16][r1 4][r2 4]
    __shared__ __align__(16) float sc2[1024];       // [i2][o2][r2]
    __shared__ __align__(16) float sA[2][2][1024];  // [buf][tok][i1][o2][r2]
    __shared__ __align__(16) float sX[2][2][256];   // [buf][tok][elem]

    const int tid    = threadIdx.x;
    const int o2     = tid & 15;
    const int z      = (tid >> 4) & 1;
    const int o1p    = tid >> 5;                    // 0..7; warp-uniform
    const int pair   = blockIdx.x & 63;
    const int oct    = blockIdx.x >> 6;             // 0..7
    const int i0base = oct * 4;                     // 4 slices per CTA

    // ---- core relayout into smem ----
    for (int idx = tid; idx < 4096; idx += THREADS) {
        int r2 = idx & 3, r1 = (idx >> 2) & 3, i1 = (idx >> 4) & 15, o1 = idx >> 8;
        sc1[idx] = g1[((r1 * 16 + o1) * 16 + i1) * 4 + r2];
    }
    for (int idx = tid; idx < 1024; idx += THREADS) {
        int r2 = idx & 3, o2g = (idx >> 2) & 15, i2 = idx >> 6;
        sc2[idx] = g2[(r2 * 16 + o2g) * 16 + i2];
    }

    const float* x0 = x + (2 * pair + 0) * 8192;
    const float* x1 = x + (2 * pair + 1) * 8192;

    sX[0][0][tid] = x0[(i0base + 0) * 256 + tid];
    sX[0][1][tid] = x1[(i0base + 0) * 256 + tid];
    sX[1][0][tid] = x0[(i0base + 1) * 256 + tid];
    sX[1][1][tid] = x1[(i0base + 1) * 256 + tid];

    const int i1prod = 2 * o1p + z;

    __syncthreads();

    step1_both(sX[0][0], sX[0][1], sA[0][0], sA[0][1], sc2, i1prod, o2);
    float xn0 = x0[(i0base + 2) * 256 + tid];
    float xn1 = x1[(i0base + 2) * 256 + tid];
    __syncthreads();

    for (int k = 0; k < 4; k++) {
        const int b = k & 1;
        const int i0 = i0base + k;

        // ---- step 2: B over own i1-half, BOTH o1, both tokens (16 acc chains) ----
        u64 acc[2][2][4];                 // [o1sel][tok][r1]
        #pragma unroll
        for (int a = 0; a < 2; a++)
            #pragma unroll
            for (int t = 0; t < 2; t++)
                #pragma unroll
                for (int r1 = 0; r1 < 4; r1++) acc[a][t][r1] = 0ull;

        const float* A0 = sA[b][0];
        const float* A1 = sA[b][1];
        #pragma unroll
        for (int s = 0; s < 8; s++) {
            const int i1 = z * 8 + s;
            const ulonglong2 av0 = *reinterpret_cast<const ulonglong2*>(
                &A0[(i1 * 16 + o2) * 4]);
            const ulonglong2 av1 = *reinterpret_cast<const ulonglong2*>(
                &A1[(i1 * 16 + o2) * 4]);
            const ulonglong2* cpA = reinterpret_cast<const ulonglong2*>(
                &sc1[(o1p * 16 + i1) * 16]);
            const ulonglong2* cpB = reinterpret_cast<const ulonglong2*>(
                &sc1[((o1p + 8) * 16 + i1) * 16]);
            #pragma unroll
            for (int r1 = 0; r1 < 4; r1++) {
                ulonglong2 cA = cpA[r1];
                ulonglong2 cB = cpB[r1];
                acc[0][0][r1] = fma2(av0.x, cA.x, acc[0][0][r1]);
                acc[0][0][r1] = fma2(av0.y, cA.y, acc[0][0][r1]);
                acc[0][1][r1] = fma2(av1.x, cA.x, acc[0][1][r1]);
                acc[0][1][r1] = fma2(av1.y, cA.y, acc[0][1][r1]);
                acc[1][0][r1] = fma2(av0.x, cB.x, acc[1][0][r1]);
                acc[1][0][r1] = fma2(av0.y, cB.y, acc[1][0][r1]);
                acc[1][1][r1] = fma2(av1.x, cB.x, acc[1][1][r1]);
                acc[1][1][r1] = fma2(av1.y, cB.y, acc[1][1][r1]);
            }
        }

        // ---- combine z-halves and write B to gmem (coalesced STG.64) ----
        #pragma unroll
        for (int a = 0; a < 2; a++) {
            const int o1 = o1p + 8 * a;
            #pragma unroll
            for (int t = 0; t < 2; t++) {
                float pr[4];
                #pragma unroll
                for (int r1 = 0; r1 < 4; r1++) {
                    float p = hadd(acc[a][t][r1]);
                    p += __shfl_xor_sync(0xffffffffu, p, 16);
                    pr[r1] = p;
                }
                u64 w = z ? pk2(pr[2], pr[3]) : pk2(pr[0], pr[1]);
                const int tok = 2 * pair + t;
                float* dst = g_B + (size_t)((o1 * 128 + tok) * 32 + i0) * 64
                           + o2 * 4 + 2 * z;
                *reinterpret_cast<u64*>(dst) = w;
            }
        }

        // ---- step 1 for slice k+1; stage slice k+2; one sync ----
        if (k < 3) {
            const int nb = (k + 1) & 1;
            step1_both(sX[nb][0], sX[nb][1], sA[nb][0], sA[nb][1], sc2, i1prod, o2);
            if (k < 2) {
                sX[b][0][tid] = xn0;
                sX[b][1][tid] = xn1;
                if (k < 1) {
                    xn0 = x0[(i0base + k + 3) * 256 + tid];
                    xn1 = x1[(i0base + k + 3) * 256 + tid];
                }
            }
            __syncthreads();
        }
    }
}

__global__ __launch_bounds__(THREADS, 4)
void tt_stageB_kernel(const float* __restrict__ g0,
                      const float* __restrict__ bias,
                      float* __restrict__ out)
{
    __shared__ __align__(16) float sBm[8192];   // [i0 32][t 4][o2 16][r1 4]
    __shared__ __align__(16) float sc0[4096];   // [i0 32][r1 4][o0 32]

    const int tid  = threadIdx.x;
    const int o1   = blockIdx.x & 15;
    const int tblk = blockIdx.x >> 4;           // 0..31 (4 tokens each)

    // load B chunk: gmem contiguous [t 4][i0 32][o2 16][r1 4] -> smem [i0][t][o2][r1]
    const float4* gb = reinterpret_cast<const float4*>(
        g_B + (size_t)o1 * 262144 + (size_t)tblk * 8192);
    float4* sb4 = reinterpret_cast<float4*>(sBm);
    #pragma unroll
    for (int j = 0; j < 8; j++) {
        int idx = tid + 256 * j;                // 0..2047 float4
        int t  = idx >> 9;
        int i0 = (idx >> 4) & 31;
        int q  = idx & 15;                      // o2; float4 spans r1 0-3
        sb4[(i0 * 4 + t) * 16 + q] = gb[idx];
    }
    // load c0: sc0[(i0*4+r1)*32 + o0] = g0[(o0*32+i0)*4 + r1]
    for (int idx = tid; idx < 4096; idx += THREADS) {
        int o0 = idx & 31, r1 = (idx >> 5) & 3, i0 = idx >> 7;
        sc0[idx] = g0[(o0 * 32 + i0) * 4 + r1];
    }
    __syncthreads();

    const int o2 = tid & 15;
    const int t  = (tid >> 4) & 3;
    const int h  = tid >> 6;                    // o0 quarter (8 o0)

    u64 y[4] = { 0ull, 0ull, 0ull, 0ull };      // 4 o0-pairs

    #pragma unroll 4
    for (int i0 = 0; i0 < 32; i0++) {
        float4 b = sb4[(i0 * 4 + t) * 16 + o2];
        float br[4] = { b.x, b.y, b.z, b.w };
        #pragma unroll
        for (int r1 = 0; r1 < 4; r1++) {
            u64 bb = pk2(br[r1], br[r1]);
            const ulonglong2* cp = reinterpret_cast<const ulonglong2*>(
                &sc0[(i0 * 4 + r1) * 32 + h * 8]);      // broadcast
            ulonglong2 c0v = cp[0];
            ulonglong2 c1v = cp[1];
            y[0] = fma2(bb, c0v.x, y[0]);
            y[1] = fma2(bb, c0v.y, y[1]);
            y[2] = fma2(bb, c1v.x, y[2]);
            y[3] = fma2(bb, c1v.y, y[3]);
        }
    }

    // epilogue: + bias, direct store
    const int col = o1 * 16 + o2;
    float* ob = out + (size_t)(tblk * 4 + t) * 8192 + (h * 8) * 256 + col;
    const float* bb = bias + (h * 8) * 256 + col;
    #pragma unroll
    for (int q = 0; q < 2; q++) {
        float f0, f1, f2, f3;
        unpk(y[2 * q],     f0, f1);
        unpk(y[2 * q + 1], f2, f3);
        ob[(4 * q + 0) * 256] = f0 + bb[(4 * q + 0) * 256];
        ob[(4 * q + 1) * 256] = f1 + bb[(4 * q + 1) * 256];
        ob[(4 * q + 2) * 256] = f2 + bb[(4 * q + 2) * 256];
        ob[(4 * q + 3) * 256] = f3 + bb[(4 * q + 3) * 256];
    }
}

extern "C" void kernel_launch(void* const* d_in, const int* in_sizes, int n_in,
                              void* d_out, int out_size)
{
    const float* x    = (const float*)d_in[0];  // [128, 8192]
    const float* g0   = (const float*)d_in[1];  // [1,32,32,4]
    const float* g1   = (const float*)d_in[2];  // [4,16,16,4]
    const float* g2   = (const float*)d_in[3];  // [4,16,16,1]
    const float* bias = (const float*)d_in[4];  // [8192]
    float* out = (float*)d_out;                 // [128, 8192]

    tt_stageA_kernel<<<512, THREADS>>>(x, g1, g2);
    tt_stageB_kernel<<<512, THREADS>>>(g0, bias, out);
}

// round 16
// speedup vs baseline: 1.9915x; 1.9915x over previous
#include <cuda_runtime.h>

// TT-linear: y = x @ W^T + bias
//   c0: [1,32(o0),32(i0),4(r1)]  c1: [4(r1),16(o1),16(i1),4(r2)]  c2: [4(r2),16(o2),16(i2),1]
//
// Kernel 0: out = bias (broadcast fill).
// Kernel 1: grid 256 = (token-pair 64) x (i0-quarter 4); 256 thr; 2 CTAs/SM; ONE wave.
//   Lane map: o2 = tid&15, z = (tid>>4)&1, o1p = tid>>5 (0..7, warp-uniform).
//   CTA covers ALL o1 (chip fma2 = minimum). Thread handles TWO o1 (o1p, o1p+8).
//   step1: thread produces A row i1=2*o1p+z, both tokens, shared c2 loads.
//   step2 (NEW): z splits R1 (2 each), all 16 i1 per thread; c1 loads are 1-wavefront
//     (z-halves hit disjoint bank quads in one 64B region); A loads warp-uniform.
//     Partner exchange of the other r1-pair via shfl_xor(16) — no barrier.
//   step3: z splits o0; c0 loads shared. ONE __syncthreads per slice.
//   Epilogue: RED.ADD into bias-prefilled out.

#define THREADS 256

typedef unsigned long long u64;

__device__ __forceinline__ u64 pk2(float lo, float hi) {
    u64 r;
    asm("mov.b64 %0, {%1, %2};" : "=l"(r) : "f"(lo), "f"(hi));
    return r;
}
__device__ __forceinline__ void unpk(u64 v, float& lo, float& hi) {
    asm("mov.b64 {%0, %1}, %2;" : "=f"(lo), "=f"(hi) : "l"(v));
}
__device__ __forceinline__ u64 fma2(u64 a, u64 b, u64 c) {
    u64 d;
    asm("fma.rn.f32x2 %0, %1, %2, %3;" : "=l"(d) : "l"(a), "l"(b), "l"(c));
    return d;
}
__device__ __forceinline__ float hadd(u64 v) {
    float lo, hi;
    unpk(v, lo, hi);
    return lo + hi;
}

// step1: A_t[i1][o2][r2] for BOTH tokens, one i1 row, shared c2 loads. (R13 verbatim)
__device__ __forceinline__ void step1_both(const float* __restrict__ Xs0,
                                           const float* __restrict__ Xs1,
                                           float* __restrict__ Ad0,
                                           float* __restrict__ Ad1,
                                           const float* __restrict__ sc2,
                                           int i1, int o2)
{
    u64 a01_0 = 0ull, a23_0 = 0ull, a01_1 = 0ull, a23_1 = 0ull;
    #pragma unroll
    for (int ch = 0; ch < 2; ch++) {
        const float4* xq0 = reinterpret_cast<const float4*>(&Xs0[i1 * 16 + ch * 8]);
        const float4* xq1 = reinterpret_cast<const float4*>(&Xs1[i1 * 16 + ch * 8]);
        float4 p0 = xq0[0], p1 = xq0[1];
        float4 q0 = xq1[0], q1 = xq1[1];
        float xs0[8] = { p0.x,p0.y,p0.z,p0.w, p1.x,p1.y,p1.z,p1.w };
        float xs1[8] = { q0.x,q0.y,q0.z,q0.w, q1.x,q1.y,q1.z,q1.w };
        #pragma unroll
        for (int j = 0; j < 8; j++) {
            const int i2 = ch * 8 + j;
            ulonglong2 c = *reinterpret_cast<const ulonglong2*>(&sc2[(i2 * 16 + o2) * 4]);
            u64 xd0 = pk2(xs0[j], xs0[j]);
            u64 xd1 = pk2(xs1[j], xs1[j]);
            a01_0 = fma2(xd0, c.x, a01_0);
            a23_0 = fma2(xd0, c.y, a23_0);
            a01_1 = fma2(xd1, c.x, a01_1);
            a23_1 = fma2(xd1, c.y, a23_1);
        }
    }
    ulonglong2 st0; st0.x = a01_0; st0.y = a23_0;
    ulonglong2 st1; st1.x = a01_1; st1.y = a23_1;
    *reinterpret_cast<ulonglong2*>(&Ad0[(i1 * 16 + o2) * 4]) = st0;
    *reinterpret_cast<ulonglong2*>(&Ad1[(i1 * 16 + o2) * 4]) = st1;
}

__global__ __launch_bounds__(THREADS, 2)
void tt_partial_kernel(const float* __restrict__ x,
                       const float* __restrict__ g0,
                       const float* __restrict__ g1,
                       const float* __restrict__ g2,
                       float* __restrict__ out)
{
    __shared__ __align__(16) float sc0[1024];       // [it 8][r1 4][o0 32]
    __shared__ __align__(16) float sc1[4096];       // [o1 16][i1 16][z 2][rr 2][r2 4]
    __shared__ __align__(16) float sc2[1024];       // [i2][o2][r2]
    __shared__ __align__(16) float sA[2][2][1024];  // [buf][tok][i1][o2][r2]
    __shared__ __align__(16) float sX[2][2][256];   // [buf][tok][elem]

    const int tid     = threadIdx.x;
    const int o2      = tid & 15;
    const int z       = (tid >> 4) & 1;
    const int o1p     = tid >> 5;                   // 0..7; warp-uniform
    const int pair    = blockIdx.x & 63;
    const int quarter = blockIdx.x >> 6;            // 0..3
    const int i0base  = quarter * 8;                // 8 slices per CTA

    // ---- core relayout into smem ----
    for (int idx = tid; idx < 1024; idx += THREADS) {
        int o0 = idx & 31, r1 = (idx >> 5) & 3, it = idx >> 7;      // it = 0..7
        sc0[idx] = g0[(o0 * 32 + i0base + it) * 4 + r1];
    }
    // sc1[((o1*16+i1)*16) + zz*8 + rr*4 + r2] = g1 at r1 = 2*zz+rr
    for (int idx = tid; idx < 4096; idx += THREADS) {
        int r2 = idx & 3, rr = (idx >> 2) & 1, zz = (idx >> 3) & 1,
            i1 = (idx >> 4) & 15, o1 = idx >> 8;
        sc1[idx] = g1[(((2 * zz + rr) * 16 + o1) * 16 + i1) * 4 + r2];
    }
    for (int idx = tid; idx < 1024; idx += THREADS) {
        int r2 = idx & 3, o2g = (idx >> 2) & 15, i2 = idx >> 6;
        sc2[idx] = g2[(r2 * 16 + o2g) * 16 + i2];
    }

    const float* x0 = x + (2 * pair + 0) * 8192;
    const float* x1 = x + (2 * pair + 1) * 8192;

    sX[0][0][tid] = x0[(i0base + 0) * 256 + tid];
    sX[0][1][tid] = x1[(i0base + 0) * 256 + tid];
    sX[1][0][tid] = x0[(i0base + 1) * 256 + tid];
    sX[1][1][tid] = x1[(i0base + 1) * 256 + tid];

    u64 yp[2][2][8];                      // [o1sel][tok][o0'-pair], own z o0-half
    #pragma unroll
    for (int a = 0; a < 2; a++)
        #pragma unroll
        for (int t = 0; t < 2; t++)
            #pragma unroll
            for (int i = 0; i < 8; i++) yp[a][t][i] = 0ull;

    const int i1prod = 2 * o1p + z;

    __syncthreads();

    step1_both(sX[0][0], sX[0][1], sA[0][0], sA[0][1], sc2, i1prod, o2);
    float xn0 = x0[(i0base + 2) * 256 + tid];
    float xn1 = x1[(i0base + 2) * 256 + tid];
    __syncthreads();

    for (int k = 0; k < 8; k++) {
        const int b = k & 1;

        // ---- step 2: B over own r1-PAIR, all 16 i1, both o1, both tokens ----
        u64 acc[2][2][2];                 // [o1sel][tok][rr]
        #pragma unroll
        for (int a = 0; a < 2; a++)
            #pragma unroll
            for (int t = 0; t < 2; t++) { acc[a][t][0] = 0ull; acc[a][t][1] = 0ull; }

        const float* A0 = sA[b][0];
        const float* A1 = sA[b][1];
        #pragma unroll
        for (int i1 = 0; i1 < 16; i1++) {
            const ulonglong2 av0 = *reinterpret_cast<const ulonglong2*>(
                &A0[(i1 * 16 + o2) * 4]);              // warp-uniform row, lane o2
            const ulonglong2 av1 = *reinterpret_cast<const ulonglong2*>(
                &A1[(i1 * 16 + o2) * 4]);
            const int baseA = (o1p * 16 + i1) * 16 + z * 8;
            const int baseB = ((o1p + 8) * 16 + i1) * 16 + z * 8;
            ulonglong2 cA0 = *reinterpret_cast<const ulonglong2*>(&sc1[baseA]);      // rr=0
            ulonglong2 cA1 = *reinterpret_cast<const ulonglong2*>(&sc1[baseA + 4]);  // rr=1
            ulonglong2 cB0 = *reinterpret_cast<const ulonglong2*>(&sc1[baseB]);
            ulonglong2 cB1 = *reinterpret_cast<const ulonglong2*>(&sc1[baseB + 4]);
            acc[0][0][0] = fma2(av0.x, cA0.x, acc[0][0][0]);
            acc[0][0][0] = fma2(av0.y, cA0.y, acc[0][0][0]);
            acc[0][0][1] = fma2(av0.x, cA1.x, acc[0][0][1]);
            acc[0][0][1] = fma2(av0.y, cA1.y, acc[0][0][1]);
            acc[0][1][0] = fma2(av1.x, cA0.x, acc[0][1][0]);
            acc[0][1][0] = fma2(av1.y, cA0.y, acc[0][1][0]);
            acc[0][1][1] = fma2(av1.x, cA1.x, acc[0][1][1]);
            acc[0][1][1] = fma2(av1.y, cA1.y, acc[0][1][1]);
            acc[1][0][0] = fma2(av0.x, cB0.x, acc[1][0][0]);
            acc[1][0][0] = fma2(av0.y, cB0.y, acc[1][0][0]);
            acc[1][0][1] = fma2(av0.x, cB1.x, acc[1][0][1]);
            acc[1][0][1] = fma2(av0.y, cB1.y, acc[1][0][1]);
            acc[1][1][0] = fma2(av1.x, cB0.x, acc[1][1][0]);
            acc[1][1][0] = fma2(av1.y, cB0.y, acc[1][1][0]);
            acc[1][1][1] = fma2(av1.x, cB1.x, acc[1][1][1]);
            acc[1][1][1] = fma2(av1.y, cB1.y, acc[1][1][1]);
        }
        // own r1-pair -> scalars; partner's pair via shfl_xor(16); build bd[4]
        u64 bd[2][2][4];
        #pragma unroll
        for (int a = 0; a < 2; a++)
            #pragma unroll
            for (int t = 0; t < 2; t++) {
                float p0 = hadd(acc[a][t][0]);          // own r1 = 2z
                float p1 = hadd(acc[a][t][1]);          // own r1 = 2z+1
                float q0 = __shfl_xor_sync(0xffffffffu, p0, 16);  // partner r1 = 2(1-z)
                float q1 = __shfl_xor_sync(0xffffffffu, p1, 16);  // partner r1 = 2(1-z)+1
                float s0 = z ? q0 : p0;                 // r1 = 0
                float s1 = z ? q1 : p1;                 // r1 = 1
                float s2 = z ? p0 : q0;                 // r1 = 2
                float s3 = z ? p1 : q1;                 // r1 = 3
                bd[a][t][0] = pk2(s0, s0);
                bd[a][t][1] = pk2(s1, s1);
                bd[a][t][2] = pk2(s2, s2);
                bd[a][t][3] = pk2(s3, s3);
            }

        // ---- step 3: own z o0-half; c0 loads shared across tok and both o1 ----
        #pragma unroll
        for (int r1 = 0; r1 < 4; r1++) {
            const ulonglong2* cq = reinterpret_cast<const ulonglong2*>(
                &sc0[k * 128 + r1 * 32 + z * 16]);
            #pragma unroll
            for (int q = 0; q < 4; q++) {
                ulonglong2 c = cq[q];                  // o0' = 4q..4q+3 within half
                yp[0][0][2 * q]     = fma2(bd[0][0][r1], c.x, yp[0][0][2 * q]);
                yp[0][0][2 * q + 1] = fma2(bd[0][0][r1], c.y, yp[0][0][2 * q + 1]);
                yp[0][1][2 * q]     = fma2(bd[0][1][r1], c.x, yp[0][1][2 * q]);
                yp[0][1][2 * q + 1] = fma2(bd[0][1][r1], c.y, yp[0][1][2 * q + 1]);
                yp[1][0][2 * q]     = fma2(bd[1][0][r1], c.x, yp[1][0][2 * q]);
                yp[1][0][2 * q + 1] = fma2(bd[1][0][r1], c.y, yp[1][0][2 * q + 1]);
                yp[1][1][2 * q]     = fma2(bd[1][1][r1], c.x, yp[1][1][2 * q]);
                yp[1][1][2 * q + 1] = fma2(bd[1][1][r1], c.y, yp[1][1][2 * q + 1]);
            }
        }

        // ---- step 1 for slice k+1; stage slice k+2; one sync ----
        if (k < 7) {
            const int nb = (k + 1) & 1;
            step1_both(sX[nb][0], sX[nb][1], sA[nb][0], sA[nb][1], sc2, i1prod, o2);
            if (k < 6) {
                sX[b][0][tid] = xn0;
                sX[b][1][tid] = xn1;
                if (k < 5) {
                    xn0 = x0[(i0base + k + 3) * 256 + tid];
                    xn1 = x1[(i0base + k + 3) * 256 + tid];
                }
            }
            __syncthreads();
        }
    }

    // ---- epilogue: RED.ADD into bias-prefilled out ----
    #pragma unroll
    for (int a = 0; a < 2; a++) {
        const int col = (o1p + 8 * a) * 16 + o2;
        #pragma unroll
        for (int t = 0; t < 2; t++) {
            float* ob = out + (size_t)(2 * pair + t) * 8192 + (z * 16) * 256 + col;
            #pragma unroll
            for (int q = 0; q < 4; q++) {
                float f0, f1, f2, f3;
                unpk(yp[a][t][2 * q],     f0, f1);
                unpk(yp[a][t][2 * q + 1], f2, f3);
                atomicAdd(ob + (4 * q + 0) * 256, f0);
                atomicAdd(ob + (4 * q + 1) * 256, f1);
                atomicAdd(ob + (4 * q + 2) * 256, f2);
                atomicAdd(ob + (4 * q + 3) * 256, f3);
            }
        }
    }
}

__global__ __launch_bounds__(128)
void tt_bias_kernel(const float* __restrict__ bias, float* __restrict__ out)
{
    // out = 262144 float4 = 128 copies of bias (2048 float4 each); grid 2048
    const int v = blockIdx.x * 128 + threadIdx.x;
    reinterpret_cast<float4*>(out)[v] =
        reinterpret_cast<const float4*>(bias)[v & 2047];
}

extern "C" void kernel_launch(void* const* d_in, const int* in_sizes, int n_in,
                              void* d_out, int out_size)
{
    const float* x    = (const float*)d_in[0];  // [128, 8192]
    const float* g0   = (const float*)d_in[1];  // [1,32,32,4]
    const float* g1   = (const float*)d_in[2];  // [4,16,16,4]
    const float* g2   = (const float*)d_in[3];  // [4,16,16,1]
    const float* bias = (const float*)d_in[4];  // [8192]
    float* out = (float*)d_out;                 // [128, 8192]

    tt_bias_kernel<<<2048, 128>>>(bias, out);
    tt_partial_kernel<<<256, THREADS>>>(x, g0, g1, g2, out);
}